// round 15
// baseline (speedup 1.0000x reference)
#include <cuda_runtime.h>
#include <cuda_bf16.h>
#include <cstdint>

// ============================================================================
// Int8Linear: out[8192,4096] = x[8192,4096] @ W^T[4096,4096] + bias
// R14: software-pipelined fragment loads. R10's structure (sync -> LDS burst
// -> MMA burst) leaves the tensor pipe idle ~40% (tensor-busy pinned ~905us
// across R9/R10/R12). Now: 16 warps x 32x32 warp tile (acc 64->32 regs) frees
// registers for FULL double-buffered A/B fragments; LDS of half-tile k+1
// overlaps MMAs of half-tile k. One barrier per k-tile, cp.async 3-stage.
// Per-output accumulation order unchanged -> rel_err canary 2.937228e-4.
//
//   Pass 0: detect weight dtype (int8 vs int32-promoted)
//   Pass 1: x fp32 -> tf32 bits (cvt.rna), 16-k-permuted, scratch gA
//   Pass 2: W dequant -> tf32 bits, 16-k-permuted, scratch gB
//   Pass 3: GEMM 128x128x32, 512 thr, warp tile 32x32, pipelined frags.
// ============================================================================

#define M_DIM  8192
#define N_DIM  4096
#define K_DIM  4096
#define MT     128
#define NT     128
#define KT     32
#define NUM_KT (K_DIM / KT)   // 128
#define STAGES 3

__device__ __align__(16) uint32_t g_xa[(size_t)M_DIM * K_DIM];  // x, tf32, k-permuted
__device__ __align__(16) uint32_t g_wb[(size_t)N_DIM * K_DIM];  // W,  tf32, k-permuted
__device__ int g_w_is_i32;

// ---------------------------------------------------------------- helpers
__device__ __forceinline__ uint32_t smem_u32(const void* p) {
    uint32_t a;
    asm("{ .reg .u64 t; cvta.to.shared.u64 t, %1; cvt.u32.u64 %0, t; }" : "=r"(a) : "l"(p));
    return a;
}
__device__ __forceinline__ uint32_t f2tf32(float f) {
    uint32_t r; asm("cvt.rna.tf32.f32 %0, %1;" : "=r"(r) : "f"(f)); return r;
}
__device__ __forceinline__ void cp_async16(uint32_t dst, const void* src) {
    asm volatile("cp.async.cg.shared.global [%0], [%1], 16;" :: "r"(dst), "l"(src));
}
#define CP_COMMIT() asm volatile("cp.async.commit_group;" ::: "memory")
#define CP_WAIT1()  asm volatile("cp.async.wait_group 1;" ::: "memory")

__device__ __forceinline__ void lds128(uint4& v, uint32_t addr) {
    asm volatile("ld.shared.v4.b32 {%0,%1,%2,%3}, [%4];"
                 : "=r"(v.x), "=r"(v.y), "=r"(v.z), "=r"(v.w) : "r"(addr));
}

__device__ __forceinline__ void mma_tf32(float (&d)[4], const uint32_t (&a)[4],
                                         const uint32_t (&b)[2]) {
    asm volatile(
        "mma.sync.aligned.m16n8k8.row.col.f32.tf32.tf32.f32 "
        "{%0,%1,%2,%3}, {%4,%5,%6,%7}, {%8,%9}, {%0,%1,%2,%3};"
        : "+f"(d[0]), "+f"(d[1]), "+f"(d[2]), "+f"(d[3])
        : "r"(a[0]), "r"(a[1]), "r"(a[2]), "r"(a[3]), "r"(b[0]), "r"(b[1]));
}

// ---------------------------------------------------------------- dtype probe
__global__ void detect_wtype_kernel(const int* __restrict__ w) {
    __shared__ int s_ok;
    if (threadIdx.x == 0) s_ok = 1;
    __syncthreads();
    #pragma unroll
    for (int i = 0; i < 4; i++) {
        int v = w[threadIdx.x + i * 256];
        if (v < -128 || v > 127) atomicAnd(&s_ok, 0);
    }
    __syncthreads();
    if (threadIdx.x == 0) g_w_is_i32 = s_ok;
}

// ---------------------------------------------------------------- preprocess
// 16-k block permuted: phys float4 p = (w[p], w[p+4], w[p+8], w[p+12]).
__global__ void cvt_x_kernel(const float4* __restrict__ x, uint4* __restrict__ out, int nblk) {
    for (int b = blockIdx.x * blockDim.x + threadIdx.x; b < nblk; b += gridDim.x * blockDim.x) {
        float4 v0 = x[b * 4 + 0], v1 = x[b * 4 + 1], v2 = x[b * 4 + 2], v3 = x[b * 4 + 3];
        uint4 o;
        o.x = f2tf32(v0.x); o.y = f2tf32(v1.x); o.z = f2tf32(v2.x); o.w = f2tf32(v3.x);
        out[b * 4 + 0] = o;
        o.x = f2tf32(v0.y); o.y = f2tf32(v1.y); o.z = f2tf32(v2.y); o.w = f2tf32(v3.y);
        out[b * 4 + 1] = o;
        o.x = f2tf32(v0.z); o.y = f2tf32(v1.z); o.z = f2tf32(v2.z); o.w = f2tf32(v3.z);
        out[b * 4 + 2] = o;
        o.x = f2tf32(v0.w); o.y = f2tf32(v1.w); o.z = f2tf32(v2.w); o.w = f2tf32(v3.w);
        out[b * 4 + 3] = o;
    }
}

__global__ void dequant_w_kernel(const void* __restrict__ wsrc, const float* __restrict__ scales,
                                 uint4* __restrict__ out, int nblk) {
    const bool i32 = (g_w_is_i32 != 0);
    for (int b = blockIdx.x * blockDim.x + threadIdx.x; b < nblk; b += gridDim.x * blockDim.x) {
        float s = __ldg(scales + (b >> 2));
        float w[16];
        if (i32) {
            const int4* p = (const int4*)wsrc + b * 4;
            #pragma unroll
            for (int j = 0; j < 4; j++) {
                int4 v = p[j];
                w[j * 4 + 0] = (float)v.x; w[j * 4 + 1] = (float)v.y;
                w[j * 4 + 2] = (float)v.z; w[j * 4 + 3] = (float)v.w;
            }
        } else {
            uint4 raw = ((const uint4*)wsrc)[b];
            uint32_t ws[4] = {raw.x, raw.y, raw.z, raw.w};
            #pragma unroll
            for (int j = 0; j < 4; j++)
                #pragma unroll
                for (int t = 0; t < 4; t++)
                    w[j * 4 + t] = (float)(int8_t)((ws[j] >> (8 * t)) & 0xFF);
        }
        #pragma unroll
        for (int p = 0; p < 4; p++) {
            uint4 o;
            o.x = f2tf32(s * w[p]);      o.y = f2tf32(s * w[p + 4]);
            o.z = f2tf32(s * w[p + 8]);  o.w = f2tf32(s * w[p + 12]);
            out[b * 4 + p] = o;
        }
    }
}

// ---------------------------------------------------------------- GEMM
static constexpr int A_STAGE_BYTES = MT * KT * 4;             // 16384
static constexpr int STAGE_BYTES   = 2 * A_STAGE_BYTES;       // 32768
static constexpr int SMEM_TOTAL    = STAGES * STAGE_BYTES;    // 98304

__global__ void __launch_bounds__(512, 1)
gemm_tf32_kernel(const uint32_t* __restrict__ gA, const uint32_t* __restrict__ gB,
                 const float* __restrict__ bias, float* __restrict__ out) {
    extern __shared__ uint32_t smem[];
    const uint32_t sb = smem_u32(smem);
    const int tid = threadIdx.x, wid = tid >> 5, lid = tid & 31;
    const int wr  = wid & 3;         // warp m index: 0..3 (32 rows)
    const int wcc = wid >> 2;        // warp n index: 0..3 (32 cols)
    const int gid = lid >> 2, kq = lid & 3;
    const int par = gid & 1;         // fragment-row parity (uniform per thread)
    const int bm = blockIdx.y, bn = blockIdx.x;

    const uint32_t* gAt0 = gA + (size_t)bm * MT * K_DIM;
    const uint32_t* gBt0 = gB + (size_t)bn * NT * K_DIM;

    // loader: A/B planes, 1024 16B chunks each, 512 threads -> 2 per plane
    auto load_tile = [&](int t, int s) {
        const uint32_t sA = sb + s * STAGE_BYTES;
        const uint32_t sB = sA + A_STAGE_BYTES;
        const uint32_t* gAt = gAt0 + t * KT;
        const uint32_t* gBt = gBt0 + t * KT;
        #pragma unroll
        for (int i = 0; i < 2; i++) {
            int ch = tid + i * 512;
            int r = ch >> 3, c4 = ch & 7;
            int cs4 = c4 ^ ((r & 1) << 2);
            cp_async16(sA + (uint32_t)((r * 8 + cs4) * 16), gAt + (size_t)r * K_DIM + c4 * 4);
        }
        #pragma unroll
        for (int i = 0; i < 2; i++) {
            int ch = tid + i * 512;
            int r = ch >> 3, c4 = ch & 7;
            int cs4 = c4 ^ ((r & 1) << 2);
            cp_async16(sB + (uint32_t)((r * 8 + cs4) * 16), gBt + (size_t)r * K_DIM + c4 * 4);
        }
    };

    // fragment double buffers (all indices compile-time after inlining)
    uint4 FA[2][2][2];   // [buf][mt][h]
    uint4 FB[2][4];      // [buf][nt]
    float acc[2][4][4];
    #pragma unroll
    for (int mt = 0; mt < 2; mt++)
        #pragma unroll
        for (int nt = 0; nt < 4; nt++)
            #pragma unroll
            for (int c = 0; c < 4; c++) acc[mt][nt][c] = 0.0f;

    auto lds_frags = [&](int s, int ks2, int buf) {
        const uint32_t base = sb + s * STAGE_BYTES;
        const int col = (ks2 * 4 + kq) ^ (par << 2);
        #pragma unroll
        for (int mt = 0; mt < 2; mt++)
            #pragma unroll
            for (int h = 0; h < 2; h++) {
                int row = wr * 32 + mt * 16 + h * 8 + gid;
                lds128(FA[buf][mt][h], base + (uint32_t)((row * 8 + col) * 16));
            }
        const uint32_t baseB = base + A_STAGE_BYTES;
        #pragma unroll
        for (int nt = 0; nt < 4; nt++) {
            int row = wcc * 32 + nt * 8 + gid;
            lds128(FB[buf][nt], baseB + (uint32_t)((row * 8 + col) * 16));
        }
    };

    auto mma_half = [&](int buf) {
        #pragma unroll
        for (int sub = 0; sub < 2; sub++)
            #pragma unroll
            for (int mt = 0; mt < 2; mt++) {
                uint32_t a[4];
                a[0] = (&FA[buf][mt][0].x)[2 * sub];
                a[1] = (&FA[buf][mt][1].x)[2 * sub];
                a[2] = (&FA[buf][mt][0].x)[2 * sub + 1];
                a[3] = (&FA[buf][mt][1].x)[2 * sub + 1];
                #pragma unroll
                for (int nt = 0; nt < 4; nt++) {
                    uint32_t b[2];
                    b[0] = (&FB[buf][nt].x)[2 * sub];
                    b[1] = (&FB[buf][nt].x)[2 * sub + 1];
                    mma_tf32(acc[mt][nt], a, b);
                }
            }
    };

    // prologue
    load_tile(0, 0); CP_COMMIT();
    load_tile(1, 1); CP_COMMIT();
    CP_WAIT1();                 // tile 0 resident
    __syncthreads();
    lds_frags(0, 0, 0);         // (t=0, ks0) -> buf0

    int cs = 0;
    #pragma unroll 1
    for (int t = 0; t < NUM_KT; t++) {
        int ns = cs + 1; if (ns == STAGES) ns = 0;
        int ls = ns + 1; if (ls == STAGES) ls = 0;

        if (t + 2 < NUM_KT) load_tile(t + 2, ls);
        CP_COMMIT();

        lds_frags(cs, 1, 1);    // (t, ks1) -> buf1, overlaps buf0 MMAs
        mma_half(0);

        CP_WAIT1();             // tile t+1 resident (only t+2's group pending)
        __syncthreads();        // all warps done reading stage of t-1

        if (t + 1 < NUM_KT) lds_frags(ns, 0, 0);  // (t+1, ks0) -> buf0
        mma_half(1);

        cs = ns;
    }

    // fused bias epilogue
    const int gcol0 = bn * NT + wcc * 32 + 2 * kq;
    #pragma unroll
    for (int mt = 0; mt < 2; mt++) {
        #pragma unroll
        for (int half = 0; half < 2; half++) {
            const int grow = bm * MT + wr * 32 + mt * 16 + gid + half * 8;
            float* op = out + (size_t)grow * N_DIM + gcol0;
            #pragma unroll
            for (int nt = 0; nt < 4; nt++) {
                const int gc = gcol0 + nt * 8;
                float2 o;
                o.x = acc[mt][nt][half * 2 + 0] + __ldg(bias + gc);
                o.y = acc[mt][nt][half * 2 + 1] + __ldg(bias + gc + 1);
                *reinterpret_cast<float2*>(op + nt * 8) = o;
            }
        }
    }
}

// ---------------------------------------------------------------- launcher
extern "C" void kernel_launch(void* const* d_in, const int* in_sizes, int n_in,
                              void* d_out, int out_size) {
    // Resolve inputs BY SIZE (unique element counts).
    const float* x      = nullptr;
    const void*  qw     = nullptr;
    const float* scales = nullptr;
    const float* bias   = nullptr;
    for (int i = 0; i < n_in; i++) {
        switch (in_sizes[i]) {
            case 33554432: x      = (const float*)d_in[i]; break;
            case 16777216: qw     = d_in[i];               break;
            case 262144:   scales = (const float*)d_in[i]; break;
            case 4096:     bias   = (const float*)d_in[i]; break;
            default: break;
        }
    }
    float* out = (float*)d_out;

    uint32_t* gA; cudaGetSymbolAddress((void**)&gA, g_xa);
    uint32_t* gB; cudaGetSymbolAddress((void**)&gB, g_wb);

    detect_wtype_kernel<<<1, 256>>>((const int*)qw);
    cvt_x_kernel<<<4096, 256>>>((const float4*)x, (uint4*)gA, (M_DIM * K_DIM) / 16);
    dequant_w_kernel<<<2048, 256>>>(qw, scales, (uint4*)gB, (N_DIM * K_DIM) / 16);

    cudaFuncSetAttribute(gemm_tf32_kernel, cudaFuncAttributeMaxDynamicSharedMemorySize, SMEM_TOTAL);
    dim3 grid(N_DIM / NT, M_DIM / MT);   // (32, 64)
    gemm_tf32_kernel<<<grid, 512, SMEM_TOTAL>>>(gA, gB, bias, out);
}